// round 16
// baseline (speedup 1.0000x reference)
#include <cuda_runtime.h>
#include <cuda_bf16.h>
#include <mma.h>
#include <math.h>

using namespace nvcuda;

#define NN 20000
#define EE 160000
#define HIDD 128
#define NHEADS 8
#define NG 64

// ---------------- scratch (device globals; no allocation) ----------------
__device__ float g_h[NN * HIDD];
__device__ float g_q[NN * 1024];
__device__ float g_k[NN * 1024];
__device__ float g_v[NN * 1024];
__device__ float g_r[NN * HIDD];
__device__ float g_att[NN * HIDD];
__device__ float g_attm[NN * HIDD];
__device__ float g_logit[EE * NHEADS];
__device__ float g_ex[EE * NHEADS];
__device__ float g_m[NN * NHEADS];
__device__ float g_den[NN * NHEADS];
__device__ double g_sum[HIDD];
__device__ double g_sq[HIDD];
__device__ float g_scale[HIDD];
__device__ float g_shift[HIDD];
__device__ float g_cnt[NG];
// bf16 split operands (R9-proven numerics: Ah*Bh + Ah*Bl + Al*Bh, err ~1.5e-5)
__device__ __nv_bfloat16 g_ah[NN * HIDD];
__device__ __nv_bfloat16 g_al[NN * HIDD];
__device__ __nv_bfloat16 g_wth[1024 * 128];
__device__ __nv_bfloat16 g_wtl[1024 * 128];

// ======== tensor-core GEMM: C[M,KO] = A[M,128] @ W[128,KO] + bias ========
// Operands as bf16 hi/lo splits; Wt transposed [KO,128] so both k-contiguous.
// 64x64 tile, 128 threads (4 warps, each 32x32 = 2x2 wmma 16x16x16 frags).
// K-loop: 3 split passes x 4 chunks of K=32, double-buffered smem (20.5KB).
#define HG_LDA 40                 // padded smem ld (elements), mult of 8
#define HG_BUF (64 * HG_LDA)      // bf16 elements per operand buffer
#define HG_SMEM (4 * HG_BUF * 2)  // 2 bufs x (A+B) x 2B = 20480 bytes

__global__ __launch_bounds__(128) void hgemm_k(
    const __nv_bfloat16* __restrict__ Ah, const __nv_bfloat16* __restrict__ Al,
    const __nv_bfloat16* __restrict__ Bh, const __nv_bfloat16* __restrict__ Bl,
    const float* __restrict__ bias, float* __restrict__ C, int M, int KO) {
    extern __shared__ char smem[];
    __nv_bfloat16* sA[2] = {(__nv_bfloat16*)smem, (__nv_bfloat16*)smem + 2 * HG_BUF};
    __nv_bfloat16* sB[2] = {(__nv_bfloat16*)smem + HG_BUF, (__nv_bfloat16*)smem + 3 * HG_BUF};
    float* sC = (float*)smem;     // reused after compute (16KB < 20.5KB)

    const int tid = threadIdx.x;
    const int row0 = blockIdx.x * 64;
    const int col0 = blockIdx.y * 64;
    // loader mapping: thread t -> row r = t>>1, 16-bf16 segment seg = t&1 (2 uint4 each)
    const int lr = tid >> 1, lseg = (tid & 1) * 16;

    const __nv_bfloat16* Ap[3] = {Ah, Ah, Al};
    const __nv_bfloat16* Bp[3] = {Bh, Bl, Bh};

    wmma::fragment<wmma::accumulator, 16, 16, 16, float> acc[2][2];
#pragma unroll
    for (int i = 0; i < 2; i++)
#pragma unroll
        for (int j = 0; j < 2; j++) wmma::fill_fragment(acc[i][j], 0.0f);

    const uint4 z4 = make_uint4(0u, 0u, 0u, 0u);
    const int gra = row0 + lr;
    const int grb = col0 + lr;   // always < KO (KO multiple of 64)

    // prologue: chunk 0 (pass 0, kc 0)
    {
        uint4 a0 = z4, a1 = z4;
        if (gra < M) {
            a0 = *(const uint4*)(Ap[0] + (size_t)gra * 128 + lseg);
            a1 = *(const uint4*)(Ap[0] + (size_t)gra * 128 + lseg + 8);
        }
        uint4 b0 = *(const uint4*)(Bp[0] + (size_t)grb * 128 + lseg);
        uint4 b1 = *(const uint4*)(Bp[0] + (size_t)grb * 128 + lseg + 8);
        *(uint4*)(sA[0] + lr * HG_LDA + lseg) = a0;
        *(uint4*)(sA[0] + lr * HG_LDA + lseg + 8) = a1;
        *(uint4*)(sB[0] + lr * HG_LDA + lseg) = b0;
        *(uint4*)(sB[0] + lr * HG_LDA + lseg + 8) = b1;
    }
    __syncthreads();

    const int wid = tid >> 5;
    const int wr = wid >> 1, wc = wid & 1;   // warp -> 32x32 subtile

    uint4 pa0, pa1, pb0, pb1;
#pragma unroll
    for (int c = 0; c < 12; c++) {
        const int cur = c & 1;
        if (c < 11) {
            const int cn = c + 1;
            const int p = cn >> 2, kc = (cn & 3) * 32;
            pa0 = z4; pa1 = z4;
            if (gra < M) {
                pa0 = *(const uint4*)(Ap[p] + (size_t)gra * 128 + kc + lseg);
                pa1 = *(const uint4*)(Ap[p] + (size_t)gra * 128 + kc + lseg + 8);
            }
            pb0 = *(const uint4*)(Bp[p] + (size_t)grb * 128 + kc + lseg);
            pb1 = *(const uint4*)(Bp[p] + (size_t)grb * 128 + kc + lseg + 8);
        }
        // compute: 2 k-steps of 16
#pragma unroll
        for (int ks = 0; ks < 32; ks += 16) {
            wmma::fragment<wmma::matrix_a, 16, 16, 16, __nv_bfloat16, wmma::row_major> fa0, fa1;
            wmma::fragment<wmma::matrix_b, 16, 16, 16, __nv_bfloat16, wmma::col_major> fb0, fb1;
            wmma::load_matrix_sync(fa0, sA[cur] + (wr * 32 + 0) * HG_LDA + ks, HG_LDA);
            wmma::load_matrix_sync(fa1, sA[cur] + (wr * 32 + 16) * HG_LDA + ks, HG_LDA);
            wmma::load_matrix_sync(fb0, sB[cur] + (wc * 32 + 0) * HG_LDA + ks, HG_LDA);
            wmma::load_matrix_sync(fb1, sB[cur] + (wc * 32 + 16) * HG_LDA + ks, HG_LDA);
            wmma::mma_sync(acc[0][0], fa0, fb0, acc[0][0]);
            wmma::mma_sync(acc[0][1], fa0, fb1, acc[0][1]);
            wmma::mma_sync(acc[1][0], fa1, fb0, acc[1][0]);
            wmma::mma_sync(acc[1][1], fa1, fb1, acc[1][1]);
        }
        if (c < 11) {
            const int nb = (c + 1) & 1;
            *(uint4*)(sA[nb] + lr * HG_LDA + lseg) = pa0;
            *(uint4*)(sA[nb] + lr * HG_LDA + lseg + 8) = pa1;
            *(uint4*)(sB[nb] + lr * HG_LDA + lseg) = pb0;
            *(uint4*)(sB[nb] + lr * HG_LDA + lseg + 8) = pb1;
        }
        __syncthreads();
    }

    // epilogue: frags -> smem (reuse) -> bias -> global
#pragma unroll
    for (int i = 0; i < 2; i++)
#pragma unroll
        for (int j = 0; j < 2; j++)
            wmma::store_matrix_sync(sC + (wr * 32 + i * 16) * 64 + wc * 32 + j * 16,
                                    acc[i][j], 64, wmma::mem_row_major);
    __syncthreads();
#pragma unroll
    for (int t = 0; t < 8; t++) {
        int idx = tid + t * 128;          // 1024 float4 tasks = 64x64
        int r = idx >> 4, q4 = idx & 15;
        int gr = row0 + r;
        if (gr < M) {
            int gc = col0 + q4 * 4;
            float4 o = *(float4*)(sC + r * 64 + q4 * 4);
            o.x += bias[gc + 0];
            o.y += bias[gc + 1];
            o.z += bias[gc + 2];
            o.w += bias[gc + 3];
            *(float4*)(C + (size_t)gr * KO + gc) = o;
        }
    }
}

// ---------------- operand split kernels (proven R9) ----------------
__global__ void asplit_k(const float* __restrict__ a, __nv_bfloat16* __restrict__ hi,
                         __nv_bfloat16* __restrict__ lo, int n) {
    int i = blockIdx.x * blockDim.x + threadIdx.x;
    if (i >= n) return;
    float v = a[i];
    __nv_bfloat16 h = __float2bfloat16(v);
    hi[i] = h;
    lo[i] = __float2bfloat16(v - __bfloat162float(h));
}

__global__ void wsplit_k(const float* __restrict__ W, __nv_bfloat16* __restrict__ th,
                         __nv_bfloat16* __restrict__ tl, int KO) {
    __shared__ float t[32][33];
    int x = threadIdx.x, y = threadIdx.y; // 32 x 8
#pragma unroll
    for (int i = 0; i < 32; i += 8) {
        int k = blockIdx.y * 32 + y + i;
        int o = blockIdx.x * 32 + x;
        t[y + i][x] = W[(size_t)k * KO + o];
    }
    __syncthreads();
#pragma unroll
    for (int i = 0; i < 32; i += 8) {
        int o = blockIdx.x * 32 + y + i;
        int k = blockIdx.y * 32 + x;
        float v = t[x][y + i];
        __nv_bfloat16 h = __float2bfloat16(v);
        th[(size_t)o * 128 + k] = h;
        tl[(size_t)o * 128 + k] = __float2bfloat16(v - __bfloat162float(h));
    }
}

// ---------------- elementwise / fill ----------------
__global__ void fill_k(float* __restrict__ p, float v, int n) {
    int i = blockIdx.x * blockDim.x + threadIdx.x;
    if (i < n) p[i] = v;
}

// ---------------- segment softmax pieces ----------------
__device__ __forceinline__ void atomicMaxF(float* addr, float val) {
    int* ia = (int*)addr;
    int old = *ia;
    while (__int_as_float(old) < val) {
        int prev = atomicCAS(ia, old, __float_as_int(val));
        if (prev == old) break;
        old = prev;
    }
}

// fused logits + segment max (layers 0-2, per-head dim 16)  [proven]
__global__ void edge_logits16max_k(const float* __restrict__ q, const float* __restrict__ k,
                                   const int* __restrict__ src, const int* __restrict__ dst,
                                   float* __restrict__ logit, float* __restrict__ m) {
    int idx = blockIdx.x * blockDim.x + threadIdx.x;
    if (idx >= EE * NHEADS) return;
    int e = idx >> 3, h = idx & 7;
    int de = dst[e];
    const float4* qp = (const float4*)(q + (size_t)de * 128 + h * 16);
    const float4* kp = (const float4*)(k + (size_t)src[e] * 128 + h * 16);
    float s = 0.f;
#pragma unroll
    for (int i = 0; i < 4; i++) {
        float4 a = qp[i], b = kp[i];
        s += a.x * b.x + a.y * b.y + a.z * b.z + a.w * b.w;
    }
    s *= 0.25f;
    logit[idx] = s;
    atomicMaxF(&m[de * NHEADS + h], s);
}

// fused logits + segment max (layer 3), block per edge, smem reduce  [proven R14]
__global__ __launch_bounds__(256) void edge_logits128max_k(
    const float* __restrict__ q, const float* __restrict__ k,
    const int* __restrict__ src, const int* __restrict__ dst,
    float* __restrict__ logit, float* __restrict__ m) {
    int e = blockIdx.x;
    int tid = threadIdx.x;
    int h = tid >> 5;
    int lane = tid & 31;
    int de = dst[e], se = src[e];
    float4 a = ((const float4*)(q + (size_t)de * 1024 + h * 128))[lane];
    float4 b = ((const float4*)(k + (size_t)se * 1024 + h * 128))[lane];
    float s = a.x * b.x + a.y * b.y + a.z * b.z + a.w * b.w;
    __shared__ float sh[256];
    sh[tid] = s;
    __syncthreads();
#pragma unroll
    for (int st = 16; st > 0; st >>= 1) {
        if (lane < st) sh[tid] += sh[tid + st];
        __syncthreads();
    }
    if (lane == 0) {
        float v = sh[h * 32] * 0.08838834764831845f;
        logit[e * NHEADS + h] = v;
        atomicMaxF(&m[de * NHEADS + h], v);
    }
}

__global__ void exp_denom_k(const float* __restrict__ logit, const int* __restrict__ dst,
                            const float* __restrict__ m, float* __restrict__ ex,
                            float* __restrict__ den) {
    int idx = blockIdx.x * blockDim.x + threadIdx.x;
    if (idx >= EE * NHEADS) return;
    int e = idx >> 3, h = idx & 7;
    float v = expf(logit[idx] - m[dst[e] * NHEADS + h]);
    ex[idx] = v;
    atomicAdd(&den[dst[e] * NHEADS + h], v);
}

__global__ void scatter128_k(const float* __restrict__ ex, const float* __restrict__ den,
                             const float* __restrict__ v, const int* __restrict__ src,
                             const int* __restrict__ dst, float* __restrict__ out) {
    int e = blockIdx.x;
    int f = threadIdx.x;
    int de = dst[e], se = src[e];
    int h = f >> 4;
    float a = ex[e * NHEADS + h] / (den[de * NHEADS + h] + 1e-16f);
    atomicAdd(&out[(size_t)de * 128 + f], a * v[(size_t)se * 128 + f]);
}

__global__ void scatter_mean1024_k(const float* __restrict__ ex, const float* __restrict__ den,
                                   const float* __restrict__ v, const int* __restrict__ src,
                                   const int* __restrict__ dst, float* __restrict__ out) {
    int e = blockIdx.x;
    int f = threadIdx.x;
    int de = dst[e], se = src[e];
    __shared__ float a[NHEADS];
    if (f < NHEADS)
        a[f] = ex[e * NHEADS + f] / (den[de * NHEADS + f] + 1e-16f) * 0.125f;
    __syncthreads();
    const float* vp = v + (size_t)se * 1024 + f;
    float s = 0.f;
#pragma unroll
    for (int h = 0; h < NHEADS; h++) s += a[h] * vp[h * 128];
    atomicAdd(&out[(size_t)de * 128 + f], s);
}

// ---------------- beta gate ----------------
__global__ void beta_gate_k(const float* __restrict__ out, const float* __restrict__ r,
                            const float* __restrict__ Wb, float* __restrict__ hnew) {
    int node = blockIdx.x;
    int f = threadIdx.x;
    float o = out[(size_t)node * 128 + f];
    float rr = r[(size_t)node * 128 + f];
    float p = o * Wb[f] + rr * Wb[128 + f] + (o - rr) * Wb[256 + f];
    __shared__ float sh[128];
    sh[f] = p;
    __syncthreads();
#pragma unroll
    for (int s = 64; s > 0; s >>= 1) {
        if (f < s) sh[f] += sh[f + s];
        __syncthreads();
    }
    float g = 1.f / (1.f + expf(-sh[0]));
    hnew[(size_t)node * 128 + f] = g * rr + (1.f - g) * o;
}

// ---------------- batch norm + relu ----------------
#define BN_ROWS 64
__global__ void bn_stats_k(const float* __restrict__ x, double* __restrict__ sum,
                           double* __restrict__ sq) {
    int f = threadIdx.x;
    int r0 = blockIdx.x * BN_ROWS;
    float s = 0.f, s2 = 0.f;
    for (int i = 0; i < BN_ROWS; i++) {
        int r = r0 + i;
        if (r < NN) {
            float v = x[(size_t)r * 128 + f];
            s += v;
            s2 += v * v;
        }
    }
    atomicAdd(&sum[f], (double)s);
    atomicAdd(&sq[f], (double)s2);
}

__global__ void bn_finalize_k(const double* __restrict__ sum, const double* __restrict__ sq,
                              const float* __restrict__ gamma, const float* __restrict__ beta,
                              float* __restrict__ scale, float* __restrict__ shift) {
    int f = threadIdx.x;
    double mu = sum[f] / (double)NN;
    double var = sq[f] / (double)NN - mu * mu;
    float rs = (float)rsqrt(var + 1e-5);
    float sc = gamma[f] * rs;
    scale[f] = sc;
    shift[f] = beta[f] - (float)mu * sc;
}

__global__ void bn_apply_relu_k(float* __restrict__ x, const float* __restrict__ scale,
                                const float* __restrict__ shift) {
    int idx = blockIdx.x * blockDim.x + threadIdx.x;
    if (idx >= NN * 128) return;
    int f = idx & 127;
    float v = x[idx] * scale[f] + shift[f];
    x[idx] = v > 0.f ? v : 0.f;
}

// BN apply + relu + bf16 hi/lo split (proven R9)
__global__ void bn_apply_relu_split_k(float* __restrict__ x, const float* __restrict__ scale,
                                      const float* __restrict__ shift,
                                      __nv_bfloat16* __restrict__ hi,
                                      __nv_bfloat16* __restrict__ lo) {
    int idx = blockIdx.x * blockDim.x + threadIdx.x;
    if (idx >= NN * 128) return;
    int f = idx & 127;
    float v = x[idx] * scale[f] + shift[f];
    v = v > 0.f ? v : 0.f;
    x[idx] = v;
    __nv_bfloat16 h = __float2bfloat16(v);
    hi[idx] = h;
    lo[idx] = __float2bfloat16(v - __bfloat162float(h));
}

// ---------------- pooling (run-accumulating, proven R14) ----------------
__global__ void pool_sum_k(const float* __restrict__ h, const int* __restrict__ batch,
                           float* __restrict__ out, float* __restrict__ cnt) {
    int f = threadIdx.x;
    int r0 = blockIdx.x * BN_ROWS;
    int curb = -1;
    float s = 0.f;
    int run = 0;
    for (int i = 0; i < BN_ROWS; i++) {
        int r = r0 + i;
        if (r >= NN) break;
        int b = batch[r];
        if (b != curb) {
            if (run > 0) {
                atomicAdd(&out[curb * 128 + f], s);
                if (f == 0) atomicAdd(&cnt[curb], (float)run);
            }
            curb = b;
            s = 0.f;
            run = 0;
        }
        s += h[(size_t)r * 128 + f];
        run++;
    }
    if (run > 0) {
        atomicAdd(&out[curb * 128 + f], s);
        if (f == 0) atomicAdd(&cnt[curb], (float)run);
    }
}

__global__ void pool_div_k(float* __restrict__ out, const float* __restrict__ cnt) {
    int idx = blockIdx.x * blockDim.x + threadIdx.x;
    if (idx >= NG * 128) return;
    out[idx] /= fmaxf(cnt[idx >> 7], 1.f);
}

// ---------------- host-side helpers ----------------
static __nv_bfloat16 *s_ah, *s_al, *s_wth, *s_wtl;

static inline void run_wsplit(const float* W, int KO) {
    dim3 grid(KO / 32, 4), blk(32, 8);
    wsplit_k<<<grid, blk>>>(W, s_wth, s_wtl, KO);
}
static inline void run_gemm(const float* bias, float* C, int M, int KO) {
    dim3 grid((M + 63) / 64, KO / 64);
    hgemm_k<<<grid, 128, HG_SMEM>>>(s_ah, s_al, s_wth, s_wtl, bias, C, M, KO);
}

extern "C" void kernel_launch(void* const* d_in, const int* in_sizes, int n_in,
                              void* d_out, int out_size) {
    const float* x = (const float*)d_in[0];
    const int* ei = (const int*)d_in[1];
    const int* src = ei;
    const int* dst = ei + EE;
    const int* batch = (const int*)d_in[2];
    const float* Wp = (const float*)d_in[3];
    const float* bp = (const float*)d_in[4];
    const float* Wq = (const float*)d_in[5];
    const float* bq = (const float*)d_in[6];
    const float* Wk = (const float*)d_in[7];
    const float* bk = (const float*)d_in[8];
    const float* Wv = (const float*)d_in[9];
    const float* bv = (const float*)d_in[10];
    const float* Ws = (const float*)d_in[11];
    const float* bs = (const float*)d_in[12];
    const float* Wbeta = (const float*)d_in[13];
    const float* Wq3 = (const float*)d_in[14];
    const float* bq3 = (const float*)d_in[15];
    const float* Wk3 = (const float*)d_in[16];
    const float* bk3 = (const float*)d_in[17];
    const float* Wv3 = (const float*)d_in[18];
    const float* bv3 = (const float*)d_in[19];
    const float* Ws3 = (const float*)d_in[20];
    const float* bs3 = (const float*)d_in[21];
    const float* Wbeta3 = (const float*)d_in[22];
    const float* bn_gamma = (const float*)d_in[23];
    const float* bn_beta = (const float*)d_in[24];
    float* out = (float*)d_out;

    float *h, *q, *k, *v, *r, *att, *attm, *logit, *ex, *m, *den, *scale, *shift, *cnt;
    double *sum, *sq;
    cudaGetSymbolAddress((void**)&h, g_h);
    cudaGetSymbolAddress((void**)&q, g_q);
    cudaGetSymbolAddress((void**)&k, g_k);
    cudaGetSymbolAddress((void**)&v, g_v);
    cudaGetSymbolAddress((void**)&r, g_r);
    cudaGetSymbolAddress((void**)&att, g_att);
    cudaGetSymbolAddress((void**)&attm, g_attm);
    cudaGetSymbolAddress((void**)&logit, g_logit);
    cudaGetSymbolAddress((void**)&ex, g_ex);
    cudaGetSymbolAddress((void**)&m, g_m);
    cudaGetSymbolAddress((void**)&den, g_den);
    cudaGetSymbolAddress((void**)&scale, g_scale);
    cudaGetSymbolAddress((void**)&shift, g_shift);
    cudaGetSymbolAddress((void**)&cnt, g_cnt);
    cudaGetSymbolAddress((void**)&sum, g_sum);
    cudaGetSymbolAddress((void**)&sq, g_sq);
    cudaGetSymbolAddress((void**)&s_ah, g_ah);
    cudaGetSymbolAddress((void**)&s_al, g_al);
    cudaGetSymbolAddress((void**)&s_wth, g_wth);
    cudaGetSymbolAddress((void**)&s_wtl, g_wtl);

    const int EH = EE * NHEADS;
    const int eh_blocks = (EH + 255) / 256;
    const int nf_blocks = (NN * 128 + 255) / 256;
    const int bn_blocks = (NN + BN_ROWS - 1) / BN_ROWS;

    // prologue: h = x @ Wp + bp
    asplit_k<<<nf_blocks, 256>>>(x, s_ah, s_al, NN * 128);
    run_wsplit(Wp, 128);
    run_gemm(bp, h, NN, 128);
    asplit_k<<<nf_blocks, 256>>>(h, s_ah, s_al, NN * 128);

    for (int L = 0; L < 3; L++) {
        run_wsplit(Wq + (size_t)L * 128 * 128, 128);
        run_gemm(bq + L * 128, q, NN, 128);
        run_wsplit(Wk + (size_t)L * 128 * 128, 128);
        run_gemm(bk + L * 128, k, NN, 128);
        run_wsplit(Wv + (size_t)L * 128 * 128, 128);
        run_gemm(bv + L * 128, v, NN, 128);
        run_wsplit(Ws + (size_t)L * 128 * 128, 128);
        run_gemm(bs + L * 128, r, NN, 128);

        fill_k<<<(NN * NHEADS + 255) / 256, 256>>>(m, -1e30f, NN * NHEADS);
        cudaMemsetAsync(den, 0, NN * NHEADS * sizeof(float));
        cudaMemsetAsync(att, 0, (size_t)NN * 128 * sizeof(float));

        edge_logits16max_k<<<eh_blocks, 256>>>(q, k, src, dst, logit, m);
        exp_denom_k<<<eh_blocks, 256>>>(logit, dst, m, ex, den);
        scatter128_k<<<EE, 128>>>(ex, den, v, src, dst, att);
        beta_gate_k<<<NN, 128>>>(att, r, Wbeta + (size_t)L * 384, h);

        cudaMemsetAsync(sum, 0, HIDD * sizeof(double));
        cudaMemsetAsync(sq, 0, HIDD * sizeof(double));
        bn_stats_k<<<bn_blocks, 128>>>(h, sum, sq);
        bn_finalize_k<<<1, 128>>>(sum, sq, bn_gamma + L * 128, bn_beta + L * 128, scale, shift);
        bn_apply_relu_split_k<<<nf_blocks, 256>>>(h, scale, shift, s_ah, s_al);
    }

    // layer 3 (heads=8, per-head dim 128, head mean fused into scatter)
    run_wsplit(Wq3, 1024);
    run_gemm(bq3, q, NN, 1024);
    run_wsplit(Wk3, 1024);
    run_gemm(bk3, k, NN, 1024);
    run_wsplit(Wv3, 1024);
    run_gemm(bv3, v, NN, 1024);
    run_wsplit(Ws3, 128);
    run_gemm(bs3, r, NN, 128);

    fill_k<<<(NN * NHEADS + 255) / 256, 256>>>(m, -1e30f, NN * NHEADS);
    cudaMemsetAsync(den, 0, NN * NHEADS * sizeof(float));
    cudaMemsetAsync(attm, 0, (size_t)NN * 128 * sizeof(float));

    edge_logits128max_k<<<EE, 256>>>(q, k, src, dst, logit, m);
    exp_denom_k<<<eh_blocks, 256>>>(logit, dst, m, ex, den);
    scatter_mean1024_k<<<EE, 128>>>(ex, den, v, src, dst, attm);
    beta_gate_k<<<NN, 128>>>(attm, r, Wbeta3, h);

    cudaMemsetAsync(sum, 0, HIDD * sizeof(double));
    cudaMemsetAsync(sq, 0, HIDD * sizeof(double));
    bn_stats_k<<<bn_blocks, 128>>>(h, sum, sq);
    bn_finalize_k<<<1, 128>>>(sum, sq, bn_gamma + 3 * 128, bn_beta + 3 * 128, scale, shift);
    bn_apply_relu_k<<<nf_blocks, 256>>>(h, scale, shift);

    // global mean pool per graph
    cudaMemsetAsync(out, 0, NG * 128 * sizeof(float));
    cudaMemsetAsync(cnt, 0, NG * sizeof(float));
    pool_sum_k<<<bn_blocks, 128>>>(h, batch, out, cnt);
    pool_div_k<<<(NG * 128 + 255) / 256, 256>>>(out, cnt);
}